// round 1
// baseline (speedup 1.0000x reference)
#include <cuda_runtime.h>

#define BB 32
#define TT_IN 1024
#define TP 1025
#define EMB 384
#define GC 96
#define NWARPS 12
#define TILE 32
#define XS_STRIDE 35   // TILE+2 rows padded to odd-ish stride -> conflict-free writes

// Scratch (device globals: no allocations allowed)
__device__ int   g_cum[BB * TP];
__device__ float g_wt[3 * GC * EMB];   // transposed weights: [k][i][c]

// ---------------------------------------------------------------------------
// Transpose conv1 weights [c][i][k] -> [k][i][c] for coalesced reads
// ---------------------------------------------------------------------------
__global__ void transpose_w_kernel(const float* __restrict__ w1) {
    int idx = blockIdx.x * blockDim.x + threadIdx.x;
    if (idx >= EMB * GC * 3) return;
    int k = idx % 3;
    int i = (idx / 3) % GC;
    int c = idx / (3 * GC);
    g_wt[(k * GC + i) * EMB + c] = w1[idx];
}

// ---------------------------------------------------------------------------
// Inclusive cumsum of durations per batch row (one block per b)
// ---------------------------------------------------------------------------
__global__ void cumsum_kernel(const int* __restrict__ dur) {
    const int b = blockIdx.x;
    const int tid = threadIdx.x;           // 256 threads
    const int CH = 5;                      // 256*5 = 1280 >= 1025
    __shared__ int part[256];

    int base = tid * CH;
    int s = 0;
#pragma unroll
    for (int j = 0; j < CH; j++) {
        int p = base + j;
        if (p < TP) s += dur[b * TP + p];
    }
    part[tid] = s;
    __syncthreads();

    // Kogge-Stone inclusive scan over 256 partials
    for (int off = 1; off < 256; off <<= 1) {
        int v = (tid >= off) ? part[tid - off] : 0;
        __syncthreads();
        part[tid] += v;
        __syncthreads();
    }

    int run = (tid > 0) ? part[tid - 1] : 0;
#pragma unroll
    for (int j = 0; j < CH; j++) {
        int p = base + j;
        if (p < TP) {
            run += dur[b * TP + p];
            g_cum[b * TP + p] = run;
        }
    }
}

// ---------------------------------------------------------------------------
// Fused duration predictor:
//   grouped conv1d(k=3, pad=1, groups=4) + bias + ReLU + dot(w2) + b2
// One block per (t-tile of 32, b). 384 threads = one output channel each.
// x tile staged in SMEM as [channel][local_t] so the inner-loop read
// xs[ch][tt+k] is a warp-wide broadcast (all lanes in a warp share the group).
// ---------------------------------------------------------------------------
extern __shared__ float s_mem[];

__global__ void conv_kernel(const float* __restrict__ ph,
                            const float* __restrict__ sil,
                            const float* __restrict__ b1,
                            const float* __restrict__ w2,
                            const float* __restrict__ b2,
                            float* __restrict__ dpred) {
    float* xs  = s_mem;                       // EMB * XS_STRIDE
    float* red = s_mem + EMB * XS_STRIDE;     // NWARPS * TILE

    const int b   = blockIdx.y;
    const int t0  = blockIdx.x * TILE;
    const int tid = threadIdx.x;              // channel c in [0,384)

    // Stage x tile: rows lt=0..TILE+1 map to global t = t0-1+lt.
    // t in [0,1023] -> phoneme; t == 1024 -> silence row; else zero pad.
#pragma unroll 2
    for (int lt = 0; lt < TILE + 2; lt++) {
        int tg = t0 - 1 + lt;
        float v = 0.f;
        if (tg >= 0 && tg < TT_IN)      v = ph[((size_t)b * TT_IN + tg) * EMB + tid];
        else if (tg == TT_IN)           v = sil[tid];
        xs[tid * XS_STRIDE + lt] = v;
    }
    __syncthreads();

    const int g = tid / GC;
    const float* xbase = xs + (g * GC) * XS_STRIDE;

    float acc[TILE];
    const float bias = b1[tid];
#pragma unroll
    for (int tt = 0; tt < TILE; tt++) acc[tt] = bias;

    const float* wt = g_wt + tid;   // [k][i][c], coalesced across threads
    for (int i = 0; i < GC; i++) {
        const float* row = xbase + i * XS_STRIDE;
#pragma unroll
        for (int k = 0; k < 3; k++) {
            float w = wt[((k * GC) + i) * EMB];
#pragma unroll
            for (int tt = 0; tt < TILE; tt++) {
                acc[tt] = fmaf(w, row[tt + k], acc[tt]);
            }
        }
    }

    // conv2 (1x1 to scalar): v = w2[c] * relu(acc); reduce over 384 channels.
    const float w2c = w2[tid];
    const int lane = tid & 31;
    const int warp = tid >> 5;
#pragma unroll
    for (int tt = 0; tt < TILE; tt++) {
        float v = w2c * fmaxf(acc[tt], 0.f);
        v += __shfl_down_sync(0xffffffffu, v, 16);
        v += __shfl_down_sync(0xffffffffu, v, 8);
        v += __shfl_down_sync(0xffffffffu, v, 4);
        v += __shfl_down_sync(0xffffffffu, v, 2);
        v += __shfl_down_sync(0xffffffffu, v, 1);
        if (lane == 0) red[warp * TILE + tt] = v;
    }
    __syncthreads();

    if (tid < TILE) {
        int t = t0 + tid;
        if (t < TP) {
            float s = b2[0];
#pragma unroll
            for (int w = 0; w < NWARPS; w++) s += red[w * TILE + tid];
            dpred[b * TP + t] = s;
        }
    }
}

// ---------------------------------------------------------------------------
// Length regulation: one warp per output frame.
// Binary search over inclusive cumsum (searchsorted side="right"),
// then copy the 384-float token row (96 float4) or write zeros.
// ---------------------------------------------------------------------------
__global__ void gather_kernel(const float* __restrict__ ph,
                              const float* __restrict__ sil,
                              float* __restrict__ out,
                              int t_out) {
    const int wglobal = (blockIdx.x * blockDim.x + threadIdx.x) >> 5;
    const int lane = threadIdx.x & 31;
    const int total = BB * t_out;
    if (wglobal >= total) return;

    const int b = wglobal / t_out;
    const int t = wglobal - b * t_out;
    const int* cum = g_cum + b * TP;

    int idx = 0, valid = 0;
    if (lane == 0) {
        int lo = 0, hi = TP - 1;           // first j with cum[j] > t (clipped)
        while (lo < hi) {
            int mid = (lo + hi) >> 1;
            if (cum[mid] > t) hi = mid; else lo = mid + 1;
        }
        idx = lo;
        valid = (t < cum[TP - 1]) ? 1 : 0;
    }
    idx   = __shfl_sync(0xffffffffu, idx, 0);
    valid = __shfl_sync(0xffffffffu, valid, 0);

    float4* dst = (float4*)(out + ((size_t)b * t_out + t) * EMB);
    if (!valid) {
        float4 z = make_float4(0.f, 0.f, 0.f, 0.f);
#pragma unroll
        for (int j = 0; j < 3; j++) dst[j * 32 + lane] = z;
        return;
    }
    const float4* src = (idx < TT_IN)
        ? (const float4*)(ph + ((size_t)b * TT_IN + idx) * EMB)
        : (const float4*)sil;
#pragma unroll
    for (int j = 0; j < 3; j++) dst[j * 32 + lane] = src[j * 32 + lane];
}

// ---------------------------------------------------------------------------
// Launch
// ---------------------------------------------------------------------------
extern "C" void kernel_launch(void* const* d_in, const int* in_sizes, int n_in,
                              void* d_out, int out_size) {
    const float* ph  = (const float*)d_in[0];   // [32,1024,384]
    const float* sil = (const float*)d_in[1];   // [384]
    const float* w1  = (const float*)d_in[2];   // [384,96,3]
    const float* b1  = (const float*)d_in[3];   // [384]
    const float* w2  = (const float*)d_in[4];   // [1,384,1]
    const float* b2  = (const float*)d_in[5];   // [1]
    const int*   dur = (const int*)d_in[6];     // [32,1025]
    // d_in[7] = t_out scalar on device: unreadable under capture; derive instead.

    const int t_out = (out_size - BB * TP) / (BB * EMB);

    float* out_exp  = (float*)d_out;                                  // [B,t_out,EMB]
    float* out_pred = (float*)d_out + (size_t)BB * t_out * EMB;       // [B,TP]

    transpose_w_kernel<<<(EMB * GC * 3 + 255) / 256, 256>>>(w1);
    cumsum_kernel<<<BB, 256>>>(dur);

    const int smem_bytes = (EMB * XS_STRIDE + NWARPS * TILE) * (int)sizeof(float);
    cudaFuncSetAttribute(conv_kernel,
                         cudaFuncAttributeMaxDynamicSharedMemorySize, smem_bytes);
    dim3 cgrid((TP + TILE - 1) / TILE, BB);
    conv_kernel<<<cgrid, EMB, smem_bytes>>>(ph, sil, b1, w2, b2, out_pred);

    const int frames = BB * t_out;
    const int threads = 256;
    const int blocks = (frames * 32 + threads - 1) / threads;
    gather_kernel<<<blocks, threads>>>(ph, sil, out_exp, t_out);
}

// round 2
// speedup vs baseline: 1.3126x; 1.3126x over previous
#include <cuda_runtime.h>

#define BB 32
#define TT_IN 1024
#define TP 1025
#define EMB 384
#define GC 96
#define NI2 48           // GC/2 input-channel pairs
#define NWARPS 12
#define CTILE 16         // time steps per conv block

// Scratch (device globals: no allocations allowed)
__device__ int    g_cum[BB * TP];
__device__ float2 g_wt2[3 * NI2 * EMB];   // [k][i2][c] -> {w[c][2i2][k], w[c][2i2+1][k]}

// Packed fp32x2 FMA (Blackwell): d.lo=a.lo*b.lo+d.lo ; d.hi=a.hi*b.hi+d.hi
#define FFMA2(acc, a, b) \
    asm("fma.rn.f32x2 %0, %1, %2, %0;" : "+l"(acc) : "l"(a), "l"(b))

// ---------------------------------------------------------------------------
// Pack conv1 weights [c][i][k] -> float2 pairs [k][i2][c]
// ---------------------------------------------------------------------------
__global__ void transpose_w_kernel(const float* __restrict__ w1) {
    int idx = blockIdx.x * blockDim.x + threadIdx.x;
    if (idx >= 3 * NI2 * EMB) return;
    int c  = idx % EMB;
    int i2 = (idx / EMB) % NI2;
    int k  = idx / (EMB * NI2);
    float2 p;
    p.x = w1[c * (GC * 3) + (2 * i2)     * 3 + k];
    p.y = w1[c * (GC * 3) + (2 * i2 + 1) * 3 + k];
    g_wt2[idx] = p;
}

// ---------------------------------------------------------------------------
// Inclusive cumsum of durations per batch row (one block per b)
// ---------------------------------------------------------------------------
__global__ void cumsum_kernel(const int* __restrict__ dur) {
    const int b = blockIdx.x;
    const int tid = threadIdx.x;           // 256 threads
    const int CH = 5;                      // 256*5 = 1280 >= 1025
    __shared__ int part[256];

    int base = tid * CH;
    int s = 0;
#pragma unroll
    for (int j = 0; j < CH; j++) {
        int p = base + j;
        if (p < TP) s += dur[b * TP + p];
    }
    part[tid] = s;
    __syncthreads();

    for (int off = 1; off < 256; off <<= 1) {
        int v = (tid >= off) ? part[tid - off] : 0;
        __syncthreads();
        part[tid] += v;
        __syncthreads();
    }

    int run = (tid > 0) ? part[tid - 1] : 0;
#pragma unroll
    for (int j = 0; j < CH; j++) {
        int p = base + j;
        if (p < TP) {
            run += dur[b * TP + p];
            g_cum[b * TP + p] = run;
        }
    }
}

// ---------------------------------------------------------------------------
// Fused duration predictor with packed f32x2 FMAs.
// Block = (t-tile of 16, b), 384 threads = one output channel each.
// x tile staged as [t][c] so {x[2i2], x[2i2+1]} is an aligned LDS.64 broadcast.
// Each b64 accumulator carries two input-channel partial sums (lo/hi).
// ---------------------------------------------------------------------------
__global__ __launch_bounds__(384, 2)
void conv_kernel(const float* __restrict__ ph,
                 const float* __restrict__ sil,
                 const float* __restrict__ b1,
                 const float* __restrict__ w2,
                 const float* __restrict__ b2,
                 float* __restrict__ dpred) {
    __shared__ float xs[(CTILE + 2) * EMB];
    __shared__ float red[NWARPS * CTILE];

    const int b   = blockIdx.y;
    const int t0  = blockIdx.x * CTILE;
    const int tid = threadIdx.x;              // output channel c

    // Stage x tile [t][c]: global t = t0-1+lt; t==1024 -> silence; else zero.
#pragma unroll
    for (int lt = 0; lt < CTILE + 2; lt++) {
        int tg = t0 - 1 + lt;
        float v = 0.f;
        if ((unsigned)tg < TT_IN)  v = ph[((size_t)b * TT_IN + tg) * EMB + tid];
        else if (tg == TT_IN)      v = sil[tid];
        xs[lt * EMB + tid] = v;
    }
    __syncthreads();

    const int cbase = (tid / GC) * GC;        // group channel base

    unsigned long long acc[CTILE];
#pragma unroll
    for (int t = 0; t < CTILE; t++) acc[t] = 0ULL;

    const unsigned long long* wb = (const unsigned long long*)g_wt2;

    for (int i2 = 0; i2 < NI2; i2++) {
        unsigned long long wk0 = wb[(0 * NI2 + i2) * EMB + tid];
        unsigned long long wk1 = wb[(1 * NI2 + i2) * EMB + tid];
        unsigned long long wk2 = wb[(2 * NI2 + i2) * EMB + tid];
        const char* xp = (const char*)&xs[cbase + 2 * i2];
#pragma unroll
        for (int t = 0; t < CTILE; t++) {
            unsigned long long x0 = *(const unsigned long long*)(xp + (t + 0) * (EMB * 4));
            unsigned long long x1 = *(const unsigned long long*)(xp + (t + 1) * (EMB * 4));
            unsigned long long x2 = *(const unsigned long long*)(xp + (t + 2) * (EMB * 4));
            FFMA2(acc[t], wk0, x0);
            FFMA2(acc[t], wk1, x1);
            FFMA2(acc[t], wk2, x2);
        }
    }

    // Epilogue: lo+hi+bias, ReLU, * w2[c], reduce over 384 channels.
    const float bias = b1[tid];
    const float w2c  = w2[tid];
    const int lane = tid & 31;
    const int warp = tid >> 5;
#pragma unroll
    for (int t = 0; t < CTILE; t++) {
        unsigned lo, hi;
        asm("mov.b64 {%0,%1}, %2;" : "=r"(lo), "=r"(hi) : "l"(acc[t]));
        float v = __uint_as_float(lo) + __uint_as_float(hi) + bias;
        v = w2c * fmaxf(v, 0.f);
        v += __shfl_down_sync(0xffffffffu, v, 16);
        v += __shfl_down_sync(0xffffffffu, v, 8);
        v += __shfl_down_sync(0xffffffffu, v, 4);
        v += __shfl_down_sync(0xffffffffu, v, 2);
        v += __shfl_down_sync(0xffffffffu, v, 1);
        if (lane == 0) red[warp * CTILE + t] = v;
    }
    __syncthreads();

    if (tid < CTILE) {
        int t = t0 + tid;
        if (t < TP) {
            float s = b2[0];
#pragma unroll
            for (int w = 0; w < NWARPS; w++) s += red[w * CTILE + tid];
            dpred[b * TP + t] = s;
        }
    }
}

// ---------------------------------------------------------------------------
// Length regulation by SCATTER: one warp per (b, token j).
// Read the 384-float row once, write it d = cum[j]-cum[j-1] times (d in 0..8).
// No binary search; every source row hits DRAM exactly once.
// ---------------------------------------------------------------------------
__global__ void scatter_kernel(const float* __restrict__ ph,
                               const float* __restrict__ sil,
                               float* __restrict__ out,
                               int t_out) {
    const int w = (blockIdx.x * blockDim.x + threadIdx.x) >> 5;
    const int lane = threadIdx.x & 31;
    if (w >= BB * TP) return;
    const int b = w / TP;
    const int j = w - b * TP;

    const int hi = g_cum[b * TP + j];
    const int lo = j ? g_cum[b * TP + j - 1] : 0;
    const int d = hi - lo;
    if (d <= 0) return;

    const float4* src = (j < TT_IN)
        ? (const float4*)(ph + ((size_t)b * TT_IN + j) * EMB)
        : (const float4*)sil;
    float4 r0 = src[lane];
    float4 r1 = src[32 + lane];
    float4 r2 = src[64 + lane];

    float4* dst = (float4*)(out + ((size_t)b * t_out + lo) * EMB);
    for (int f = 0; f < d; f++, dst += EMB / 4) {
        dst[lane]      = r0;
        dst[32 + lane] = r1;
        dst[64 + lane] = r2;
    }
}

// Zero-fill frames past each batch's total length (out buffer is poisoned).
__global__ void zerotail_kernel(float* __restrict__ out, int t_out) {
    const int b = blockIdx.x;
    const int tot = g_cum[b * TP + TP - 1];
    if (tot >= t_out) return;
    float4* dst = (float4*)(out + ((size_t)b * t_out + tot) * EMB);
    const int n4 = (t_out - tot) * (EMB / 4);
    const float4 z = make_float4(0.f, 0.f, 0.f, 0.f);
    for (int i = threadIdx.x; i < n4; i += blockDim.x) dst[i] = z;
}

// ---------------------------------------------------------------------------
// Launch
// ---------------------------------------------------------------------------
extern "C" void kernel_launch(void* const* d_in, const int* in_sizes, int n_in,
                              void* d_out, int out_size) {
    const float* ph  = (const float*)d_in[0];   // [32,1024,384]
    const float* sil = (const float*)d_in[1];   // [384]
    const float* w1  = (const float*)d_in[2];   // [384,96,3]
    const float* b1  = (const float*)d_in[3];   // [384]
    const float* w2  = (const float*)d_in[4];   // [1,384,1]
    const float* b2  = (const float*)d_in[5];   // [1]
    const int*   dur = (const int*)d_in[6];     // [32,1025]

    const int t_out = (out_size - BB * TP) / (BB * EMB);

    float* out_exp  = (float*)d_out;                             // [B,t_out,EMB]
    float* out_pred = (float*)d_out + (size_t)BB * t_out * EMB;  // [B,TP]

    transpose_w_kernel<<<(3 * NI2 * EMB + 255) / 256, 256>>>(w1);
    cumsum_kernel<<<BB, 256>>>(dur);

    dim3 cgrid((TP + CTILE - 1) / CTILE, BB);
    conv_kernel<<<cgrid, EMB>>>(ph, sil, b1, w2, b2, out_pred);

    const int warps = BB * TP;
    scatter_kernel<<<(warps * 32 + 255) / 256, 256>>>(ph, sil, out_exp, t_out);
    zerotail_kernel<<<BB, 256>>>(out_exp, t_out);
}